// round 1
// baseline (speedup 1.0000x reference)
#include <cuda_runtime.h>
#include <math.h>

#define T_    128
#define BSZ   1024
#define IN_   75
#define H_    128
#define G4_   512
#define OUT_  256
#define MDEC  (128*75)
#define EPS_  1e-5f

// ---------------- device scratch (no runtime allocation allowed) ----------------
__device__ float g_xTm [(size_t)T_*IN_*BSZ];   // 37.5 MB  (T, IN, B)  time-major transposed input
__device__ float g_XT  [(size_t)T_*G4_*BSZ];   // 256  MB  (T, 4H, B)  x@Wih result, reused for both layers
__device__ float g_hs0T[(size_t)T_*H_*BSZ];    // 64   MB  (T, H, B)   layer-0 hidden stream
__device__ float g_hT  [(size_t)H_*BSZ];       // layer-1 hidden state
__device__ float g_cT  [(size_t)H_*BSZ];       // cell state (per layer, reused)
__device__ float g_GhT [(size_t)G4_*BSZ];      // per-step h@Whh (transposed)
__device__ float g_xsA [(size_t)T_*G4_];       // folded BN-x scale
__device__ float g_xsB [(size_t)T_*G4_];       // folded BN-x bias (+ b + bhh)
__device__ float g_embT[(size_t)OUT_*BSZ];     // fc output (OUT, B)

// ---------------- transpose sequences (B,T,IN) -> (T,IN,B) ----------------
__global__ __launch_bounds__(256) void transpose_seq(const float* __restrict__ seq,
                                                     float* __restrict__ xTm)
{
    int t  = blockIdx.y;
    int b0 = blockIdx.x * 128;
    __shared__ float sm[128 * 77];
    int tid = threadIdx.x;
    for (int i = tid; i < 128 * IN_; i += 256) {
        int bl = i / IN_, k = i % IN_;
        sm[bl * 77 + k] = seq[(size_t)(b0 + bl) * (T_ * IN_) + (size_t)t * IN_ + k];
    }
    __syncthreads();
    for (int i = tid; i < IN_ * 128; i += 256) {
        int k = i / 128, bl = i % 128;
        xTm[(size_t)t * IN_ * BSZ + (size_t)k * BSZ + b0 + bl] = sm[bl * 77 + k];
    }
}

// ---------------- generic TN SGEMM: C[n][b] = sum_k W[k][n] * A[k][b] ----------------
// W: (K,N) n-contiguous.  A: (K,Bd) b-contiguous.  C: (N,Bd) b-contiguous.
// All of N, Bd divisible by 64. K arbitrary (zero-padded tail).
__global__ __launch_bounds__(256) void tn_gemm(const float* __restrict__ W,
                                               const float* __restrict__ A,
                                               float* __restrict__ C,
                                               int K, int N, int Bd,
                                               long long strideA, long long strideC,
                                               const float* __restrict__ bias_n,
                                               const float* __restrict__ bias_b)
{
    int z = blockIdx.z;
    A += (size_t)z * strideA;
    C += (size_t)z * strideC;
    int n0 = blockIdx.y * 64;
    int b0 = blockIdx.x * 64;

    __shared__ float Ws[16][64];
    __shared__ float As[16][64];

    int tid = threadIdx.x;
    int tx = tid % 16, ty = tid / 16;
    int lk  = tid / 16;        // k-row within tile
    int lc4 = (tid % 16) * 4;  // col within tile

    float acc[4][4];
#pragma unroll
    for (int i = 0; i < 4; i++)
#pragma unroll
        for (int j = 0; j < 4; j++) acc[i][j] = 0.f;

    for (int k0 = 0; k0 < K; k0 += 16) {
        int krow = k0 + lk;
        float4 wv = make_float4(0.f, 0.f, 0.f, 0.f);
        float4 av = make_float4(0.f, 0.f, 0.f, 0.f);
        if (krow < K) {
            wv = *(const float4*)&W[(size_t)krow * N  + n0 + lc4];
            av = *(const float4*)&A[(size_t)krow * Bd + b0 + lc4];
        }
        *(float4*)&Ws[lk][lc4] = wv;
        *(float4*)&As[lk][lc4] = av;
        __syncthreads();
#pragma unroll
        for (int kk = 0; kk < 16; kk++) {
            float wr[4], ar[4];
            *(float4*)wr = *(const float4*)&Ws[kk][ty * 4];
            *(float4*)ar = *(const float4*)&As[kk][tx * 4];
#pragma unroll
            for (int i = 0; i < 4; i++)
#pragma unroll
                for (int j = 0; j < 4; j++) acc[i][j] += wr[i] * ar[j];
        }
        __syncthreads();
    }

#pragma unroll
    for (int i = 0; i < 4; i++) {
        int n = n0 + ty * 4 + i;
        float bn = bias_n ? bias_n[n] : 0.f;
        float4 o;
        o.x = acc[i][0] + bn; o.y = acc[i][1] + bn;
        o.z = acc[i][2] + bn; o.w = acc[i][3] + bn;
        if (bias_b) {
            int bb = b0 + tx * 4;
            o.x += bias_b[bb + 0]; o.y += bias_b[bb + 1];
            o.z += bias_b[bb + 2]; o.w += bias_b[bb + 3];
        }
        *(float4*)&C[(size_t)n * Bd + b0 + tx * 4] = o;
    }
}

// ---------------- per-(t,n) BN stats of XT, folded into affine (a,b) ----------------
__global__ __launch_bounds__(256) void x_stats(const float* __restrict__ XT,
                                               const float* __restrict__ gih,
                                               const float* __restrict__ bih,
                                               const float* __restrict__ bgate,
                                               const float* __restrict__ bhh,
                                               float* __restrict__ xsA,
                                               float* __restrict__ xsB)
{
    size_t idx = blockIdx.x;                    // t*512 + n
    const float* col = XT + idx * BSZ;
    int tid = threadIdx.x, lane = tid & 31, wid = tid >> 5;
    float s = 0.f, q = 0.f;
    for (int i = tid; i < BSZ; i += 256) { float v = col[i]; s += v; q += v * v; }
    __shared__ float wb[8][3];
#pragma unroll
    for (int o = 16; o > 0; o >>= 1) {
        s += __shfl_down_sync(0xffffffffu, s, o);
        q += __shfl_down_sync(0xffffffffu, q, o);
    }
    if (lane == 0) { wb[wid][0] = s; wb[wid][1] = q; }
    __syncthreads();
    if (tid == 0) {
        float S = 0.f, Q = 0.f;
        for (int w = 0; w < 8; w++) { S += wb[w][0]; Q += wb[w][1]; }
        float m = S * (1.f / BSZ);
        float var = Q * (1.f / BSZ) - m * m;
        float r = rsqrtf(var + EPS_);
        int n = (int)(idx % G4_);
        xsA[idx] = gih[n] * r;
        xsB[idx] = bih[n] - gih[n] * r * m + bgate[n] + bhh[n];
    }
}

__device__ __forceinline__ float sigm(float x) { return 1.f / (1.f + __expf(-x)); }

// ---------------- fused BN-LSTM step: gate BN + cell update + cell BN + h ----------------
// Block j owns hidden column j (all B rows) and its 4 gate columns {j, j+H, j+2H, j+3H}.
__global__ __launch_bounds__(256) void bnlstm_step(const float* __restrict__ XTt,
                                                   const float* __restrict__ xsA,
                                                   const float* __restrict__ xsB,
                                                   const float* __restrict__ GhT,
                                                   const float* __restrict__ ghh,
                                                   const float* __restrict__ gc,
                                                   const float* __restrict__ bc,
                                                   float* __restrict__ cT,
                                                   float* __restrict__ hT,
                                                   int first)
{
    int j = blockIdx.x;
    int tid = threadIdx.x;
    int lane = tid & 31, wid = tid >> 5;

    __shared__ float wb[8][9];
    __shared__ float stat[8];

    float gv[4][4];
    float gate[4][4];
    float mh[4], rh[4];

    if (!first) {
        float acc[8];
#pragma unroll
        for (int v = 0; v < 8; v++) acc[v] = 0.f;
#pragma unroll
        for (int q = 0; q < 4; q++) {
            const float* col = GhT + (size_t)(j + H_ * q) * BSZ;
#pragma unroll
            for (int r = 0; r < 4; r++) {
                float v = col[tid + 256 * r];
                gv[q][r] = v;
                acc[q] += v; acc[4 + q] += v * v;
            }
        }
#pragma unroll
        for (int v = 0; v < 8; v++) {
            float x = acc[v];
#pragma unroll
            for (int o = 16; o > 0; o >>= 1) x += __shfl_down_sync(0xffffffffu, x, o);
            if (lane == 0) wb[wid][v] = x;
        }
        __syncthreads();
        if (tid < 8) {
            float s = 0.f;
#pragma unroll
            for (int w = 0; w < 8; w++) s += wb[w][tid];
            stat[tid] = s;
        }
        __syncthreads();
#pragma unroll
        for (int q = 0; q < 4; q++) {
            float m = stat[q] * (1.f / BSZ);
            float var = stat[4 + q] * (1.f / BSZ) - m * m;
            mh[q] = m;
            rh[q] = rsqrtf(var + EPS_);
        }
    }

#pragma unroll
    for (int q = 0; q < 4; q++) {
        int n = j + H_ * q;
        float xa = xsA[n], xb = xsB[n];
        float gr = first ? 0.f : ghh[n] * rh[q];
#pragma unroll
        for (int r = 0; r < 4; r++) {
            float g = xa * XTt[(size_t)n * BSZ + tid + 256 * r] + xb;
            if (!first) g += gr * (gv[q][r] - mh[q]);
            gate[q][r] = g;
        }
    }

    float c1[4];
    float cacc0 = 0.f, cacc1 = 0.f;
#pragma unroll
    for (int r = 0; r < 4; r++) {
        int b = tid + 256 * r;
        float co = first ? 0.f : cT[(size_t)j * BSZ + b];
        float cv = sigm(gate[0][r]) * co + sigm(gate[1][r]) * tanhf(gate[3][r]);
        c1[r] = cv;
        cacc0 += cv; cacc1 += cv * cv;
        cT[(size_t)j * BSZ + b] = cv;
    }

    __syncthreads();   // protect wb/stat reuse
    {
        float x = cacc0, y = cacc1;
#pragma unroll
        for (int o = 16; o > 0; o >>= 1) {
            x += __shfl_down_sync(0xffffffffu, x, o);
            y += __shfl_down_sync(0xffffffffu, y, o);
        }
        if (lane == 0) { wb[wid][0] = x; wb[wid][1] = y; }
    }
    __syncthreads();
    if (tid < 2) {
        float s = 0.f;
#pragma unroll
        for (int w = 0; w < 8; w++) s += wb[w][tid];
        stat[tid] = s;
    }
    __syncthreads();

    float mc = stat[0] * (1.f / BSZ);
    float vc = stat[1] * (1.f / BSZ) - mc * mc;
    float rc = rsqrtf(vc + EPS_);
    float gj = gc[j], bj = bc[j];
#pragma unroll
    for (int r = 0; r < 4; r++) {
        float h = sigm(gate[2][r]) * tanhf(gj * rc * (c1[r] - mc) + bj);
        hT[(size_t)j * BSZ + tid + 256 * r] = h;
    }
}

// ---------------- launch ----------------
extern "C" void kernel_launch(void* const* d_in, const int* in_sizes, int n_in,
                              void* d_out, int out_size)
{
    const float* seq  = (const float*)d_in[0];
    const float* Wih0 = (const float*)d_in[1];
    const float* Whh0 = (const float*)d_in[2];
    const float* b0   = (const float*)d_in[3];
    const float* gih0 = (const float*)d_in[4];
    const float* bih0 = (const float*)d_in[5];
    const float* ghh0 = (const float*)d_in[6];
    const float* bhh0 = (const float*)d_in[7];
    const float* gc0  = (const float*)d_in[8];
    const float* bc0  = (const float*)d_in[9];
    const float* Wih1 = (const float*)d_in[10];
    const float* Whh1 = (const float*)d_in[11];
    const float* b1   = (const float*)d_in[12];
    const float* gih1 = (const float*)d_in[13];
    const float* bih1 = (const float*)d_in[14];
    const float* ghh1 = (const float*)d_in[15];
    const float* bhh1 = (const float*)d_in[16];
    const float* gc1  = (const float*)d_in[17];
    const float* bc1  = (const float*)d_in[18];
    const float* fcw  = (const float*)d_in[19];
    const float* fcb  = (const float*)d_in[20];
    const float* decw = (const float*)d_in[21];
    const float* decb = (const float*)d_in[22];
    float* out = (float*)d_out;
    (void)in_sizes; (void)n_in; (void)out_size;

    float *xTm, *XT, *hs0T, *hT, *cT, *GhT, *xsA, *xsB, *embT;
    cudaGetSymbolAddress((void**)&xTm,  g_xTm);
    cudaGetSymbolAddress((void**)&XT,   g_XT);
    cudaGetSymbolAddress((void**)&hs0T, g_hs0T);
    cudaGetSymbolAddress((void**)&hT,   g_hT);
    cudaGetSymbolAddress((void**)&cT,   g_cT);
    cudaGetSymbolAddress((void**)&GhT,  g_GhT);
    cudaGetSymbolAddress((void**)&xsA,  g_xsA);
    cudaGetSymbolAddress((void**)&xsB,  g_xsB);
    cudaGetSymbolAddress((void**)&embT, g_embT);

    // 1. transpose input to (T, IN, B)
    transpose_seq<<<dim3(BSZ / 128, T_), 256>>>(seq, xTm);

    // 2. layer-0 input GEMM + folded BN stats
    tn_gemm<<<dim3(BSZ / 64, G4_ / 64, T_), 256>>>(Wih0, xTm, XT, IN_, G4_, BSZ,
                                                   (long long)IN_ * BSZ, (long long)G4_ * BSZ,
                                                   nullptr, nullptr);
    x_stats<<<T_ * G4_, 256>>>(XT, gih0, bih0, b0, bhh0, xsA, xsB);

    // 3. layer-0 recurrence (h stream stored into hs0T)
    for (int t = 0; t < T_; t++) {
        if (t > 0)
            tn_gemm<<<dim3(BSZ / 64, G4_ / 64, 1), 256>>>(Whh0, hs0T + (size_t)(t - 1) * H_ * BSZ,
                                                          GhT, H_, G4_, BSZ, 0, 0, nullptr, nullptr);
        bnlstm_step<<<H_, 256>>>(XT + (size_t)t * G4_ * BSZ, xsA + (size_t)t * G4_,
                                 xsB + (size_t)t * G4_, GhT, ghh0, gc0, bc0,
                                 cT, hs0T + (size_t)t * H_ * BSZ, t == 0 ? 1 : 0);
    }

    // 4. layer-1 input GEMM + folded BN stats (XT reused)
    tn_gemm<<<dim3(BSZ / 64, G4_ / 64, T_), 256>>>(Wih1, hs0T, XT, H_, G4_, BSZ,
                                                   (long long)H_ * BSZ, (long long)G4_ * BSZ,
                                                   nullptr, nullptr);
    x_stats<<<T_ * G4_, 256>>>(XT, gih1, bih1, b1, bhh1, xsA, xsB);

    // 5. layer-1 recurrence (single hT state buffer, final t kept)
    for (int t = 0; t < T_; t++) {
        if (t > 0)
            tn_gemm<<<dim3(BSZ / 64, G4_ / 64, 1), 256>>>(Whh1, hT, GhT, H_, G4_, BSZ,
                                                          0, 0, nullptr, nullptr);
        bnlstm_step<<<H_, 256>>>(XT + (size_t)t * G4_ * BSZ, xsA + (size_t)t * G4_,
                                 xsB + (size_t)t * G4_, GhT, ghh1, gc1, bc1,
                                 cT, hT, t == 0 ? 1 : 0);
    }

    // 6. fc: embT[o][b] = sum_k fc_w[k][o] * hT[k][b] + fc_b[o]
    tn_gemm<<<dim3(BSZ / 64, OUT_ / 64, 1), 256>>>(fcw, hT, embT, H_, OUT_, BSZ,
                                                   0, 0, fcb, nullptr);

    // 7. decoder: out[b][m] = sum_o embT[o][b] * dec_w[o][m] + dec_b[m]
    //    (same TN kernel: W=embT (K=256,N=1024 b-contig), A=dec_w (K=256,Bd=9600), C=out)
    tn_gemm<<<dim3(MDEC / 64, BSZ / 64, 1), 256>>>(embT, decw, out, OUT_, BSZ, MDEC,
                                                   0, 0, nullptr, decb);
}

// round 2
// speedup vs baseline: 1.0080x; 1.0080x over previous
#include <cuda_runtime.h>
#include <math.h>

#define T_    128
#define BSZ   1024
#define IN_   75
#define H_    128
#define G4_   512
#define OUT_  256
#define MDEC  (128*75)
#define EPS_  1e-5f

// ---------------- device scratch (no runtime allocation allowed) ----------------
__device__ float g_xTm [(size_t)T_*IN_*BSZ];   // 37.5 MB  (T, IN, B)  time-major transposed input
__device__ float g_XT  [(size_t)T_*G4_*BSZ];   // 256  MB  (T, 4H, B)  x@Wih result, reused for both layers
__device__ float g_hs0T[(size_t)T_*H_*BSZ];    // 64   MB  (T, H, B)   layer-0 hidden stream
__device__ float g_hT  [(size_t)H_*BSZ];       // layer-1 hidden state
__device__ float g_cT  [(size_t)H_*BSZ];       // cell state (per layer, reused)
__device__ float g_GhT [(size_t)G4_*BSZ];      // per-step h@Whh (transposed)
__device__ float g_xsA [(size_t)T_*G4_];       // folded BN-x scale
__device__ float g_xsB [(size_t)T_*G4_];       // folded BN-x bias (+ b + bhh)
__device__ float g_embT[(size_t)OUT_*BSZ];     // fc output (OUT, B)

// ---------------- transpose sequences (B,T,IN) -> (T,IN,B) ----------------
__global__ __launch_bounds__(256) void transpose_seq(const float* __restrict__ seq,
                                                     float* __restrict__ xTm)
{
    int t  = blockIdx.y;
    int b0 = blockIdx.x * 128;
    __shared__ float sm[128 * 77];
    int tid = threadIdx.x;
    for (int i = tid; i < 128 * IN_; i += 256) {
        int bl = i / IN_, k = i % IN_;
        sm[bl * 77 + k] = seq[(size_t)(b0 + bl) * (T_ * IN_) + (size_t)t * IN_ + k];
    }
    __syncthreads();
    for (int i = tid; i < IN_ * 128; i += 256) {
        int k = i / 128, bl = i % 128;
        xTm[(size_t)t * IN_ * BSZ + (size_t)k * BSZ + b0 + bl] = sm[bl * 77 + k];
    }
}

// ---------------- generic TN SGEMM: C[n][b] = sum_k W[k][n] * A[k][b] ----------------
// W: (K,N) n-contiguous.  A: (K,Bd) b-contiguous.  C: (N,Bd) b-contiguous.
// All of N, Bd divisible by 64. K arbitrary (zero-padded tail).
__global__ __launch_bounds__(256) void tn_gemm(const float* __restrict__ W,
                                               const float* __restrict__ A,
                                               float* __restrict__ C,
                                               int K, int N, int Bd,
                                               long long strideA, long long strideC,
                                               const float* __restrict__ bias_n,
                                               const float* __restrict__ bias_b)
{
    int z = blockIdx.z;
    A += (size_t)z * strideA;
    C += (size_t)z * strideC;
    int n0 = blockIdx.y * 64;
    int b0 = blockIdx.x * 64;

    __shared__ float Ws[16][64];
    __shared__ float As[16][64];

    int tid = threadIdx.x;
    int tx = tid % 16, ty = tid / 16;
    int lk  = tid / 16;        // k-row within tile
    int lc4 = (tid % 16) * 4;  // col within tile

    float acc[4][4];
#pragma unroll
    for (int i = 0; i < 4; i++)
#pragma unroll
        for (int j = 0; j < 4; j++) acc[i][j] = 0.f;

    for (int k0 = 0; k0 < K; k0 += 16) {
        int krow = k0 + lk;
        float4 wv = make_float4(0.f, 0.f, 0.f, 0.f);
        float4 av = make_float4(0.f, 0.f, 0.f, 0.f);
        if (krow < K) {
            wv = *(const float4*)&W[(size_t)krow * N  + n0 + lc4];
            av = *(const float4*)&A[(size_t)krow * Bd + b0 + lc4];
        }
        *(float4*)&Ws[lk][lc4] = wv;
        *(float4*)&As[lk][lc4] = av;
        __syncthreads();
#pragma unroll
        for (int kk = 0; kk < 16; kk++) {
            float wr[4], ar[4];
            *(float4*)wr = *(const float4*)&Ws[kk][ty * 4];
            *(float4*)ar = *(const float4*)&As[kk][tx * 4];
#pragma unroll
            for (int i = 0; i < 4; i++)
#pragma unroll
                for (int j = 0; j < 4; j++) acc[i][j] += wr[i] * ar[j];
        }
        __syncthreads();
    }

#pragma unroll
    for (int i = 0; i < 4; i++) {
        int n = n0 + ty * 4 + i;
        float bn = bias_n ? bias_n[n] : 0.f;
        float4 o;
        o.x = acc[i][0] + bn; o.y = acc[i][1] + bn;
        o.z = acc[i][2] + bn; o.w = acc[i][3] + bn;
        if (bias_b) {
            int bb = b0 + tx * 4;
            o.x += bias_b[bb + 0]; o.y += bias_b[bb + 1];
            o.z += bias_b[bb + 2]; o.w += bias_b[bb + 3];
        }
        *(float4*)&C[(size_t)n * Bd + b0 + tx * 4] = o;
    }
}

// ---------------- per-(t,n) BN stats of XT, folded into affine (a,b) ----------------
__global__ __launch_bounds__(256) void x_stats(const float* __restrict__ XT,
                                               const float* __restrict__ gih,
                                               const float* __restrict__ bih,
                                               const float* __restrict__ bgate,
                                               const float* __restrict__ bhh,
                                               float* __restrict__ xsA,
                                               float* __restrict__ xsB)
{
    size_t idx = blockIdx.x;                    // t*512 + n
    const float* col = XT + idx * BSZ;
    int tid = threadIdx.x, lane = tid & 31, wid = tid >> 5;
    float s = 0.f, q = 0.f;
    for (int i = tid; i < BSZ; i += 256) { float v = col[i]; s += v; q += v * v; }
    __shared__ float wb[8][3];
#pragma unroll
    for (int o = 16; o > 0; o >>= 1) {
        s += __shfl_down_sync(0xffffffffu, s, o);
        q += __shfl_down_sync(0xffffffffu, q, o);
    }
    if (lane == 0) { wb[wid][0] = s; wb[wid][1] = q; }
    __syncthreads();
    if (tid == 0) {
        float S = 0.f, Q = 0.f;
        for (int w = 0; w < 8; w++) { S += wb[w][0]; Q += wb[w][1]; }
        float m = S * (1.f / BSZ);
        float var = Q * (1.f / BSZ) - m * m;
        float r = rsqrtf(var + EPS_);
        int n = (int)(idx % G4_);
        xsA[idx] = gih[n] * r;
        xsB[idx] = bih[n] - gih[n] * r * m + bgate[n] + bhh[n];
    }
}

__device__ __forceinline__ float sigm(float x) { return 1.f / (1.f + __expf(-x)); }

// ---------------- fused BN-LSTM step: gate BN + cell update + cell BN + h ----------------
// Block j owns hidden column j (all B rows) and its 4 gate columns {j, j+H, j+2H, j+3H}.
__global__ __launch_bounds__(256) void bnlstm_step(const float* __restrict__ XTt,
                                                   const float* __restrict__ xsA,
                                                   const float* __restrict__ xsB,
                                                   const float* __restrict__ GhT,
                                                   const float* __restrict__ ghh,
                                                   const float* __restrict__ gc,
                                                   const float* __restrict__ bc,
                                                   float* __restrict__ cT,
                                                   float* __restrict__ hT,
                                                   int first)
{
    int j = blockIdx.x;
    int tid = threadIdx.x;
    int lane = tid & 31, wid = tid >> 5;

    __shared__ float wb[8][9];
    __shared__ float stat[8];

    float gv[4][4];
    float gate[4][4];
    float mh[4], rh[4];

    if (!first) {
        float acc[8];
#pragma unroll
        for (int v = 0; v < 8; v++) acc[v] = 0.f;
#pragma unroll
        for (int q = 0; q < 4; q++) {
            const float* col = GhT + (size_t)(j + H_ * q) * BSZ;
#pragma unroll
            for (int r = 0; r < 4; r++) {
                float v = col[tid + 256 * r];
                gv[q][r] = v;
                acc[q] += v; acc[4 + q] += v * v;
            }
        }
#pragma unroll
        for (int v = 0; v < 8; v++) {
            float x = acc[v];
#pragma unroll
            for (int o = 16; o > 0; o >>= 1) x += __shfl_down_sync(0xffffffffu, x, o);
            if (lane == 0) wb[wid][v] = x;
        }
        __syncthreads();
        if (tid < 8) {
            float s = 0.f;
#pragma unroll
            for (int w = 0; w < 8; w++) s += wb[w][tid];
            stat[tid] = s;
        }
        __syncthreads();
#pragma unroll
        for (int q = 0; q < 4; q++) {
            float m = stat[q] * (1.f / BSZ);
            float var = stat[4 + q] * (1.f / BSZ) - m * m;
            mh[q] = m;
            rh[q] = rsqrtf(var + EPS_);
        }
    }

#pragma unroll
    for (int q = 0; q < 4; q++) {
        int n = j + H_ * q;
        float xa = xsA[n], xb = xsB[n];
        float gr = first ? 0.f : ghh[n] * rh[q];
#pragma unroll
        for (int r = 0; r < 4; r++) {
            float g = xa * XTt[(size_t)n * BSZ + tid + 256 * r] + xb;
            if (!first) g += gr * (gv[q][r] - mh[q]);
            gate[q][r] = g;
        }
    }

    float c1[4];
    float cacc0 = 0.f, cacc1 = 0.f;
#pragma unroll
    for (int r = 0; r < 4; r++) {
        int b = tid + 256 * r;
        float co = first ? 0.f : cT[(size_t)j * BSZ + b];
        float cv = sigm(gate[0][r]) * co + sigm(gate[1][r]) * tanhf(gate[3][r]);
        c1[r] = cv;
        cacc0 += cv; cacc1 += cv * cv;
        cT[(size_t)j * BSZ + b] = cv;
    }

    __syncthreads();   // protect wb/stat reuse
    {
        float x = cacc0, y = cacc1;
#pragma unroll
        for (int o = 16; o > 0; o >>= 1) {
            x += __shfl_down_sync(0xffffffffu, x, o);
            y += __shfl_down_sync(0xffffffffu, y, o);
        }
        if (lane == 0) { wb[wid][0] = x; wb[wid][1] = y; }
    }
    __syncthreads();
    if (tid < 2) {
        float s = 0.f;
#pragma unroll
        for (int w = 0; w < 8; w++) s += wb[w][tid];
        stat[tid] = s;
    }
    __syncthreads();

    float mc = stat[0] * (1.f / BSZ);
    float vc = stat[1] * (1.f / BSZ) - mc * mc;
    float rc = rsqrtf(vc + EPS_);
    float gj = gc[j], bj = bc[j];
#pragma unroll
    for (int r = 0; r < 4; r++) {
        float h = sigm(gate[2][r]) * tanhf(gj * rc * (c1[r] - mc) + bj);
        hT[(size_t)j * BSZ + tid + 256 * r] = h;
    }
}

// ---------------- launch ----------------
extern "C" void kernel_launch(void* const* d_in, const int* in_sizes, int n_in,
                              void* d_out, int out_size)
{
    const float* seq  = (const float*)d_in[0];
    const float* Wih0 = (const float*)d_in[1];
    const float* Whh0 = (const float*)d_in[2];
    const float* b0   = (const float*)d_in[3];
    const float* gih0 = (const float*)d_in[4];
    const float* bih0 = (const float*)d_in[5];
    const float* ghh0 = (const float*)d_in[6];
    const float* bhh0 = (const float*)d_in[7];
    const float* gc0  = (const float*)d_in[8];
    const float* bc0  = (const float*)d_in[9];
    const float* Wih1 = (const float*)d_in[10];
    const float* Whh1 = (const float*)d_in[11];
    const float* b1   = (const float*)d_in[12];
    const float* gih1 = (const float*)d_in[13];
    const float* bih1 = (const float*)d_in[14];
    const float* ghh1 = (const float*)d_in[15];
    const float* bhh1 = (const float*)d_in[16];
    const float* gc1  = (const float*)d_in[17];
    const float* bc1  = (const float*)d_in[18];
    const float* fcw  = (const float*)d_in[19];
    const float* fcb  = (const float*)d_in[20];
    const float* decw = (const float*)d_in[21];
    const float* decb = (const float*)d_in[22];
    float* out = (float*)d_out;
    (void)in_sizes; (void)n_in; (void)out_size;

    float *xTm, *XT, *hs0T, *hT, *cT, *GhT, *xsA, *xsB, *embT;
    cudaGetSymbolAddress((void**)&xTm,  g_xTm);
    cudaGetSymbolAddress((void**)&XT,   g_XT);
    cudaGetSymbolAddress((void**)&hs0T, g_hs0T);
    cudaGetSymbolAddress((void**)&hT,   g_hT);
    cudaGetSymbolAddress((void**)&cT,   g_cT);
    cudaGetSymbolAddress((void**)&GhT,  g_GhT);
    cudaGetSymbolAddress((void**)&xsA,  g_xsA);
    cudaGetSymbolAddress((void**)&xsB,  g_xsB);
    cudaGetSymbolAddress((void**)&embT, g_embT);

    // 1. transpose input to (T, IN, B)
    transpose_seq<<<dim3(BSZ / 128, T_), 256>>>(seq, xTm);

    // 2. layer-0 input GEMM + folded BN stats
    tn_gemm<<<dim3(BSZ / 64, G4_ / 64, T_), 256>>>(Wih0, xTm, XT, IN_, G4_, BSZ,
                                                   (long long)IN_ * BSZ, (long long)G4_ * BSZ,
                                                   nullptr, nullptr);
    x_stats<<<T_ * G4_, 256>>>(XT, gih0, bih0, b0, bhh0, xsA, xsB);

    // 3. layer-0 recurrence (h stream stored into hs0T)
    for (int t = 0; t < T_; t++) {
        if (t > 0)
            tn_gemm<<<dim3(BSZ / 64, G4_ / 64, 1), 256>>>(Whh0, hs0T + (size_t)(t - 1) * H_ * BSZ,
                                                          GhT, H_, G4_, BSZ, 0, 0, nullptr, nullptr);
        bnlstm_step<<<H_, 256>>>(XT + (size_t)t * G4_ * BSZ, xsA + (size_t)t * G4_,
                                 xsB + (size_t)t * G4_, GhT, ghh0, gc0, bc0,
                                 cT, hs0T + (size_t)t * H_ * BSZ, t == 0 ? 1 : 0);
    }

    // 4. layer-1 input GEMM + folded BN stats (XT reused)
    tn_gemm<<<dim3(BSZ / 64, G4_ / 64, T_), 256>>>(Wih1, hs0T, XT, H_, G4_, BSZ,
                                                   (long long)H_ * BSZ, (long long)G4_ * BSZ,
                                                   nullptr, nullptr);
    x_stats<<<T_ * G4_, 256>>>(XT, gih1, bih1, b1, bhh1, xsA, xsB);

    // 5. layer-1 recurrence (single hT state buffer, final t kept)
    for (int t = 0; t < T_; t++) {
        if (t > 0)
            tn_gemm<<<dim3(BSZ / 64, G4_ / 64, 1), 256>>>(Whh1, hT, GhT, H_, G4_, BSZ,
                                                          0, 0, nullptr, nullptr);
        bnlstm_step<<<H_, 256>>>(XT + (size_t)t * G4_ * BSZ, xsA + (size_t)t * G4_,
                                 xsB + (size_t)t * G4_, GhT, ghh1, gc1, bc1,
                                 cT, hT, t == 0 ? 1 : 0);
    }

    // 6. fc: embT[o][b] = sum_k fc_w[k][o] * hT[k][b] + fc_b[o]
    tn_gemm<<<dim3(BSZ / 64, OUT_ / 64, 1), 256>>>(fcw, hT, embT, H_, OUT_, BSZ,
                                                   0, 0, fcb, nullptr);

    // 7. decoder: out[b][m] = sum_o embT[o][b] * dec_w[o][m] + dec_b[m]
    //    (same TN kernel: W=embT (K=256,N=1024 b-contig), A=dec_w (K=256,Bd=9600), C=out)
    tn_gemm<<<dim3(MDEC / 64, BSZ / 64, 1), 256>>>(embT, decw, out, OUT_, BSZ, MDEC,
                                                   0, 0, nullptr, decb);
}

// round 3
// speedup vs baseline: 1.3227x; 1.3121x over previous
#include <cuda_runtime.h>
#include <math.h>

#define T_    128
#define BSZ   1024
#define IN_   75
#define H_    128
#define G4_   512
#define OUT_  256
#define MDEC  (128*75)
#define EPS_  1e-5f
#define NBLK  128
#define NTHR  512

// ---------------- device scratch (no runtime allocation allowed) ----------------
__device__ float g_xTm [(size_t)T_*IN_*BSZ];   // (T, IN, B)  time-major transposed input
__device__ float g_XT  [(size_t)T_*G4_*BSZ];   // (T, 4H, B)  x@Wih result, reused for both layers
__device__ float g_hs0T[(size_t)T_*H_*BSZ];    // (T, H, B)   layer-0 hidden stream
__device__ float g_hs1T[(size_t)T_*H_*BSZ];    // (T, H, B)   layer-1 hidden stream
__device__ float g_xsA [(size_t)T_*G4_];       // folded BN-x scale
__device__ float g_xsB [(size_t)T_*G4_];       // folded BN-x bias (+ b + bhh)
__device__ float g_embT[(size_t)OUT_*BSZ];     // fc output (OUT, B)
__device__ unsigned g_barArr;                  // grid-barrier arrival counter

__global__ void reset_bar_k() { g_barArr = 0u; }

// ---------------- transpose sequences (B,T,IN) -> (T,IN,B) ----------------
__global__ __launch_bounds__(256) void transpose_seq(const float* __restrict__ seq,
                                                     float* __restrict__ xTm)
{
    int t  = blockIdx.y;
    int b0 = blockIdx.x * 128;
    __shared__ float sm[128 * 77];
    int tid = threadIdx.x;
    for (int i = tid; i < 128 * IN_; i += 256) {
        int bl = i / IN_, k = i % IN_;
        sm[bl * 77 + k] = seq[(size_t)(b0 + bl) * (T_ * IN_) + (size_t)t * IN_ + k];
    }
    __syncthreads();
    for (int i = tid; i < IN_ * 128; i += 256) {
        int k = i / 128, bl = i % 128;
        xTm[(size_t)t * IN_ * BSZ + (size_t)k * BSZ + b0 + bl] = sm[bl * 77 + k];
    }
}

// ---------------- generic TN SGEMM: C[n][b] = sum_k W[k][n] * A[k][b] ----------------
__global__ __launch_bounds__(256) void tn_gemm(const float* __restrict__ W,
                                               const float* __restrict__ A,
                                               float* __restrict__ C,
                                               int K, int N, int Bd,
                                               long long strideA, long long strideC,
                                               const float* __restrict__ bias_n,
                                               const float* __restrict__ bias_b)
{
    int z = blockIdx.z;
    A += (size_t)z * strideA;
    C += (size_t)z * strideC;
    int n0 = blockIdx.y * 64;
    int b0 = blockIdx.x * 64;

    __shared__ float Ws[16][64];
    __shared__ float As[16][64];

    int tid = threadIdx.x;
    int tx = tid % 16, ty = tid / 16;
    int lk  = tid / 16;
    int lc4 = (tid % 16) * 4;

    float acc[4][4];
#pragma unroll
    for (int i = 0; i < 4; i++)
#pragma unroll
        for (int j = 0; j < 4; j++) acc[i][j] = 0.f;

    for (int k0 = 0; k0 < K; k0 += 16) {
        int krow = k0 + lk;
        float4 wv = make_float4(0.f, 0.f, 0.f, 0.f);
        float4 av = make_float4(0.f, 0.f, 0.f, 0.f);
        if (krow < K) {
            wv = *(const float4*)&W[(size_t)krow * N  + n0 + lc4];
            av = *(const float4*)&A[(size_t)krow * Bd + b0 + lc4];
        }
        *(float4*)&Ws[lk][lc4] = wv;
        *(float4*)&As[lk][lc4] = av;
        __syncthreads();
#pragma unroll
        for (int kk = 0; kk < 16; kk++) {
            float wr[4], ar[4];
            *(float4*)wr = *(const float4*)&Ws[kk][ty * 4];
            *(float4*)ar = *(const float4*)&As[kk][tx * 4];
#pragma unroll
            for (int i = 0; i < 4; i++)
#pragma unroll
                for (int j = 0; j < 4; j++) acc[i][j] += wr[i] * ar[j];
        }
        __syncthreads();
    }

#pragma unroll
    for (int i = 0; i < 4; i++) {
        int n = n0 + ty * 4 + i;
        float bn = bias_n ? bias_n[n] : 0.f;
        float4 o;
        o.x = acc[i][0] + bn; o.y = acc[i][1] + bn;
        o.z = acc[i][2] + bn; o.w = acc[i][3] + bn;
        if (bias_b) {
            int bb = b0 + tx * 4;
            o.x += bias_b[bb + 0]; o.y += bias_b[bb + 1];
            o.z += bias_b[bb + 2]; o.w += bias_b[bb + 3];
        }
        *(float4*)&C[(size_t)n * Bd + b0 + tx * 4] = o;
    }
}

// ---------------- per-(t,n) BN stats of XT, folded into affine (a,b) ----------------
__global__ __launch_bounds__(256) void x_stats(const float* __restrict__ XT,
                                               const float* __restrict__ gih,
                                               const float* __restrict__ bih,
                                               const float* __restrict__ bgate,
                                               const float* __restrict__ bhh,
                                               float* __restrict__ xsA,
                                               float* __restrict__ xsB)
{
    size_t idx = blockIdx.x;                    // t*512 + n
    const float* col = XT + idx * BSZ;
    int tid = threadIdx.x, lane = tid & 31, wid = tid >> 5;
    float s = 0.f, q = 0.f;
    for (int i = tid; i < BSZ; i += 256) { float v = col[i]; s += v; q += v * v; }
    __shared__ float wb[8][3];
#pragma unroll
    for (int o = 16; o > 0; o >>= 1) {
        s += __shfl_down_sync(0xffffffffu, s, o);
        q += __shfl_down_sync(0xffffffffu, q, o);
    }
    if (lane == 0) { wb[wid][0] = s; wb[wid][1] = q; }
    __syncthreads();
    if (tid == 0) {
        float S = 0.f, Q = 0.f;
        for (int w = 0; w < 8; w++) { S += wb[w][0]; Q += wb[w][1]; }
        float m = S * (1.f / BSZ);
        float var = Q * (1.f / BSZ) - m * m;
        float r = rsqrtf(var + EPS_);
        int n = (int)(idx % G4_);
        xsA[idx] = gih[n] * r;
        xsB[idx] = bih[n] - gih[n] * r * m + bgate[n] + bhh[n];
    }
}

__device__ __forceinline__ float sigm(float x) { return 1.f / (1.f + __expf(-x)); }

// ---------------- persistent fused BN-LSTM layer ----------------
// 128 co-resident blocks; block j owns hidden unit j (4 gate columns) over all B.
// Per step: in-register GEMM vs h(t-1), block-local gate BN, cell update,
// block-local cell BN, h write, one software grid barrier.
__global__ __launch_bounds__(NTHR, 1) void bnlstm_layer(
    const float* __restrict__ XT,
    const float* __restrict__ xsA,
    const float* __restrict__ xsB,
    const float* __restrict__ Whh,
    const float* __restrict__ ghh,
    const float* __restrict__ gc,
    const float* __restrict__ bc,
    float* __restrict__ hsOut)
{
    const int j = blockIdx.x;
    const int tid = threadIdx.x;
    const int lane = tid & 31, wid = tid >> 5;
    const int b0 = tid * 2;

    __shared__ float WhhS[512];        // [k][q] for this block's 4 gate columns
    __shared__ float red[16][8];
    __shared__ float stat[8];

    // Preload Whh columns {j, j+H, j+2H, j+3H}: WhhS[k*4+q] = Whh[k][j+128q]
    WhhS[tid] = Whh[(size_t)(tid >> 2) * G4_ + j + H_ * (tid & 3)];
    float ghq[4];
#pragma unroll
    for (int q = 0; q < 4; q++) ghq[q] = ghh[j + H_ * q];
    const float gcj = gc[j], bcj = bc[j];
    __syncthreads();

    float cc0 = 0.f, cc1 = 0.f;        // cell state for this thread's 2 batch cols
    unsigned barTarget = 0;

    for (int t = 0; t < T_; t++) {
        // Prefetch x-side gate values + per-step folded BN coefficients
        const float* Xt = XT + (size_t)t * G4_ * BSZ;
        float2 xv[4];
        float xa[4], xb[4];
#pragma unroll
        for (int q = 0; q < 4; q++) {
            const int n = j + H_ * q;
            xv[q] = *(const float2*)&Xt[(size_t)n * BSZ + b0];
            xa[q] = xsA[t * G4_ + n];
            xb[q] = xsB[t * G4_ + n];
        }

        float gate[4][2];
        if (t == 0) {
            // BN(0 @ Whh) contributes only bhh, already folded into xsB
#pragma unroll
            for (int q = 0; q < 4; q++) {
                gate[q][0] = fmaf(xa[q], xv[q].x, xb[q]);
                gate[q][1] = fmaf(xa[q], xv[q].y, xb[q]);
            }
        } else {
            // GEMM: Gh[q][b] = sum_k Whh[k][j+128q] * h(t-1)[k][b]
            const float* hp = hsOut + (size_t)(t - 1) * H_ * BSZ + b0;
            float a00=0.f,a01=0.f,a10=0.f,a11=0.f,a20=0.f,a21=0.f,a30=0.f,a31=0.f;
#pragma unroll 8
            for (int k = 0; k < H_; k++) {
                const float2 hv = *(const float2*)&hp[(size_t)k * BSZ];
                const float4 wv = *(const float4*)&WhhS[k * 4];
                a00 = fmaf(wv.x, hv.x, a00); a01 = fmaf(wv.x, hv.y, a01);
                a10 = fmaf(wv.y, hv.x, a10); a11 = fmaf(wv.y, hv.y, a11);
                a20 = fmaf(wv.z, hv.x, a20); a21 = fmaf(wv.z, hv.y, a21);
                a30 = fmaf(wv.w, hv.x, a30); a31 = fmaf(wv.w, hv.y, a31);
            }
            float acc[4][2] = {{a00,a01},{a10,a11},{a20,a21},{a30,a31}};

            // Block-local BN stats over all B for the 4 gate columns
            float vals[8];
#pragma unroll
            for (int q = 0; q < 4; q++) {
                vals[q]     = acc[q][0] + acc[q][1];
                vals[4 + q] = acc[q][0]*acc[q][0] + acc[q][1]*acc[q][1];
            }
#pragma unroll
            for (int v = 0; v < 8; v++) {
                float x = vals[v];
#pragma unroll
                for (int o = 16; o > 0; o >>= 1) x += __shfl_down_sync(0xffffffffu, x, o);
                if (lane == 0) red[wid][v] = x;
            }
            __syncthreads();
            if (tid < 8) {
                float s = 0.f;
#pragma unroll
                for (int w = 0; w < 16; w++) s += red[w][tid];
                stat[tid] = s;
            }
            __syncthreads();
#pragma unroll
            for (int q = 0; q < 4; q++) {
                const float m   = stat[q] * (1.f / BSZ);
                const float var = stat[4 + q] * (1.f / BSZ) - m * m;
                const float gr  = ghq[q] * rsqrtf(var + EPS_);
                gate[q][0] = fmaf(xa[q], xv[q].x, xb[q]) + gr * (acc[q][0] - m);
                gate[q][1] = fmaf(xa[q], xv[q].y, xb[q]) + gr * (acc[q][1] - m);
            }
        }

        // Cell update (gate order f,i,o,g)
        cc0 = sigm(gate[0][0]) * cc0 + sigm(gate[1][0]) * tanhf(gate[3][0]);
        cc1 = sigm(gate[0][1]) * cc1 + sigm(gate[1][1]) * tanhf(gate[3][1]);
        float cs = cc0 + cc1;
        float cq = cc0 * cc0 + cc1 * cc1;
#pragma unroll
        for (int o = 16; o > 0; o >>= 1) {
            cs += __shfl_down_sync(0xffffffffu, cs, o);
            cq += __shfl_down_sync(0xffffffffu, cq, o);
        }
        __syncthreads();               // all reads of gate-phase stat/red done
        if (lane == 0) { red[wid][0] = cs; red[wid][1] = cq; }
        __syncthreads();
        if (tid < 2) {
            float s = 0.f;
#pragma unroll
            for (int w = 0; w < 16; w++) s += red[w][tid];
            stat[tid] = s;
        }
        __syncthreads();

        const float mc = stat[0] * (1.f / BSZ);
        const float rc = rsqrtf(stat[1] * (1.f / BSZ) - mc * mc + EPS_);
        float2 hv;
        hv.x = sigm(gate[2][0]) * tanhf(fmaf(gcj * rc, cc0 - mc, bcj));
        hv.y = sigm(gate[2][1]) * tanhf(fmaf(gcj * rc, cc1 - mc, bcj));
        *(float2*)&hsOut[(size_t)t * H_ * BSZ + (size_t)j * BSZ + b0] = hv;

        // Grid barrier: h(t) visible before any block starts step t+1's GEMM
        if (t < T_ - 1) {
            barTarget += NBLK;
            if (tid == 0) {
                __threadfence();
                atomicAdd(&g_barArr, 1u);
                while (*((volatile unsigned*)&g_barArr) < barTarget) __nanosleep(64);
                __threadfence();
            }
            __syncthreads();
        }
    }
}

// ---------------- launch ----------------
extern "C" void kernel_launch(void* const* d_in, const int* in_sizes, int n_in,
                              void* d_out, int out_size)
{
    const float* seq  = (const float*)d_in[0];
    const float* Wih0 = (const float*)d_in[1];
    const float* Whh0 = (const float*)d_in[2];
    const float* b0   = (const float*)d_in[3];
    const float* gih0 = (const float*)d_in[4];
    const float* bih0 = (const float*)d_in[5];
    const float* ghh0 = (const float*)d_in[6];
    const float* bhh0 = (const float*)d_in[7];
    const float* gc0  = (const float*)d_in[8];
    const float* bc0  = (const float*)d_in[9];
    const float* Wih1 = (const float*)d_in[10];
    const float* Whh1 = (const float*)d_in[11];
    const float* b1   = (const float*)d_in[12];
    const float* gih1 = (const float*)d_in[13];
    const float* bih1 = (const float*)d_in[14];
    const float* ghh1 = (const float*)d_in[15];
    const float* bhh1 = (const float*)d_in[16];
    const float* gc1  = (const float*)d_in[17];
    const float* bc1  = (const float*)d_in[18];
    const float* fcw  = (const float*)d_in[19];
    const float* fcb  = (const float*)d_in[20];
    const float* decw = (const float*)d_in[21];
    const float* decb = (const float*)d_in[22];
    float* out = (float*)d_out;
    (void)in_sizes; (void)n_in; (void)out_size;

    float *xTm, *XT, *hs0T, *hs1T, *xsA, *xsB, *embT;
    cudaGetSymbolAddress((void**)&xTm,  g_xTm);
    cudaGetSymbolAddress((void**)&XT,   g_XT);
    cudaGetSymbolAddress((void**)&hs0T, g_hs0T);
    cudaGetSymbolAddress((void**)&hs1T, g_hs1T);
    cudaGetSymbolAddress((void**)&xsA,  g_xsA);
    cudaGetSymbolAddress((void**)&xsB,  g_xsB);
    cudaGetSymbolAddress((void**)&embT, g_embT);

    // 1. transpose input to (T, IN, B)
    transpose_seq<<<dim3(BSZ / 128, T_), 256>>>(seq, xTm);

    // 2. layer-0 input GEMM + folded BN stats
    tn_gemm<<<dim3(BSZ / 64, G4_ / 64, T_), 256>>>(Wih0, xTm, XT, IN_, G4_, BSZ,
                                                   (long long)IN_ * BSZ, (long long)G4_ * BSZ,
                                                   nullptr, nullptr);
    x_stats<<<T_ * G4_, 256>>>(XT, gih0, bih0, b0, bhh0, xsA, xsB);

    // 3. layer-0 recurrence: one persistent kernel
    reset_bar_k<<<1, 1>>>();
    bnlstm_layer<<<NBLK, NTHR>>>(XT, xsA, xsB, Whh0, ghh0, gc0, bc0, hs0T);

    // 4. layer-1 input GEMM + folded BN stats (XT reused)
    tn_gemm<<<dim3(BSZ / 64, G4_ / 64, T_), 256>>>(Wih1, hs0T, XT, H_, G4_, BSZ,
                                                   (long long)H_ * BSZ, (long long)G4_ * BSZ,
                                                   nullptr, nullptr);
    x_stats<<<T_ * G4_, 256>>>(XT, gih1, bih1, b1, bhh1, xsA, xsB);

    // 5. layer-1 recurrence
    reset_bar_k<<<1, 1>>>();
    bnlstm_layer<<<NBLK, NTHR>>>(XT, xsA, xsB, Whh1, ghh1, gc1, bc1, hs1T);

    // 6. fc on last hidden of layer 1
    tn_gemm<<<dim3(BSZ / 64, OUT_ / 64, 1), 256>>>(fcw, hs1T + (size_t)(T_ - 1) * H_ * BSZ,
                                                   embT, H_, OUT_, BSZ,
                                                   0, 0, fcb, nullptr);

    // 7. decoder
    tn_gemm<<<dim3(MDEC / 64, BSZ / 64, 1), 256>>>(embT, decw, out, OUT_, BSZ, MDEC,
                                                   0, 0, nullptr, decb);
}